// round 9
// baseline (speedup 1.0000x reference)
#include <cuda_runtime.h>
#include <cstdint>
#include <cfloat>

#define BHn   64
#define TQn   1024
#define TKn   1024
#define DKn   64
#define QT    32      // queries per block
#define KTILE 256     // key/value tile rows staged in smem
#define NTHR  512     // 16 warps
#define KST   68      // K/V/Q row stride: 68%32=4 -> conflict-free strided f4 loads
#define SCST  1028    // score row stride: 1028%32=4

// smem layout (floats): qsh[32][68] | kvsh[256][68] | scsh[32][1028] | mbias[1024] | invsh[32]
#define QSH_F   (QT*KST)                 // 2176
#define KVSH_F  (KTILE*KST)              // 17408
#define SCSH_F  (QT*SCST)                // 32896
#define SMEM_FLOATS (QSH_F + KVSH_F + SCSH_F + TKn + 32)
#define SMEM_BYTES  (SMEM_FLOATS * 4)    // 214144 B -> 1 block/SM

// ---------------------------------------------------------------------------
__device__ int g_mask_narrow;

__global__ void detect_mask_kernel(const unsigned int* __restrict__ mw) {
    __shared__ int found;
    if (threadIdx.x == 0) found = 0;
    __syncthreads();
    int local = 0;
    for (int i = threadIdx.x; i < (BHn * TKn) / 4; i += blockDim.x) {
        if (mw[i] & 0xFFFFFF00u) local = 1;
    }
    if (local) atomicOr(&found, 1);
    __syncthreads();
    if (threadIdx.x == 0) g_mask_narrow = found;
}

// packed dual-fp32 FMA (ptxas never emits FFMA2 from C++)
__device__ __forceinline__ float2 ffma2(float2 a, float2 b, float2 c) {
    float2 d;
    asm("fma.rn.f32x2 %0, %1, %2, %3;"
        : "=l"(reinterpret_cast<unsigned long long&>(d))
        : "l"(reinterpret_cast<unsigned long long&>(a)),
          "l"(reinterpret_cast<unsigned long long&>(b)),
          "l"(reinterpret_cast<unsigned long long&>(c)));
    return d;
}

__device__ __forceinline__ unsigned int smem_u32(const void* p) {
    return (unsigned int)__cvta_generic_to_shared(p);
}
__device__ __forceinline__ void cp16(unsigned int dst, const void* src) {
    asm volatile("cp.async.cg.shared.global [%0], [%1], 16;" :: "r"(dst), "l"(src));
}
// stage one KTILE x 64 tile (256 rows x 16 float4), 8 cp.async per thread
__device__ __forceinline__ void stage_tile(unsigned int kv_u32, const float4* __restrict__ g, int t) {
    #pragma unroll
    for (int i = 0; i < 8; i++) {
        int idx = t + i * NTHR;            // 0..4095
        int r = idx >> 4, c4 = idx & 15;
        cp16(kv_u32 + (unsigned int)(r * KST + 4 * c4) * 4u, g + idx);
    }
    asm volatile("cp.async.commit_group;");
}
__device__ __forceinline__ void wait_all() {
    asm volatile("cp.async.wait_group 0;" ::: "memory");
}

// ---------------------------------------------------------------------------
// one block = 32 queries x one bh head, 16 warps
// warp w = (qh, kw): qh = w>>3 (query half), kw = w&7 (k 32-row slice)
// ---------------------------------------------------------------------------
extern "C" __global__ void __launch_bounds__(NTHR, 1)
attn_fp32x2_kernel(const float* __restrict__ Q, const float* __restrict__ K,
                   const float* __restrict__ V, const unsigned char* __restrict__ Mb,
                   const int* __restrict__ pHA, const int* __restrict__ pNH,
                   float* __restrict__ Out, int write_w)
{
    extern __shared__ float sm[];
    float* qsh   = sm;                       // [QT][KST]
    float* kvsh  = sm + QSH_F;               // [KTILE][KST] (later: 16 x [16][68] partials)
    float* scsh  = kvsh + KVSH_F;            // [QT][SCST]
    float* mbias = scsh + SCSH_F;            // [1024] : 0 or -FLT_MAX
    float* invsh = mbias + TKn;              // [32]

    const int t  = threadIdx.x;
    const int w  = t >> 5;                   // warp 0..15
    const int l  = t & 31;
    const int qh = w >> 3;                   // 0,1
    const int kw = w & 7;                    // 0..7
    const int bh = blockIdx.y;
    const int q0 = blockIdx.x * QT;

    const int nh = pNH[0];
    const int ha = pHA[0];

    float* Wout      = Out + (size_t)BHn * TQn * DKn;
    float* wrow_base = Wout + ((size_t)bh * TQn + q0) * TKn;
    float* orow_base = Out  + ((size_t)bh * TQn + q0) * DKn;

    // ---- head ablation: weights and output exactly zero ----
    if (nh > 0 && (bh % nh) == ha) {
        float4 z = make_float4(0.f, 0.f, 0.f, 0.f);
        if (write_w) {
            float4* w4 = (float4*)wrow_base;
            #pragma unroll 4
            for (int i = t; i < QT * TKn / 4; i += NTHR) w4[i] = z;
        }
        ((float4*)orow_base)[t] = z;         // 512 float4 = 32x64 floats
        return;
    }

    const int shift = g_mask_narrow ? 0 : 2;
    const unsigned char* mrow = Mb + (((size_t)bh * TKn) << shift);

    const float4* Kg = (const float4*)(K + ((size_t)bh * TKn) * DKn);
    const float4* Vg = (const float4*)(V + ((size_t)bh * TKn) * DKn);
    const unsigned int kv_u32 = smem_u32(kvsh);

    // kick off K tile 0 immediately
    stage_tile(kv_u32, Kg, t);

    // ---- mask bias row: 0 if attended, -FLT_MAX if masked ----
    #pragma unroll
    for (int i = 0; i < 2; i++) {
        int k = t + i * NTHR;
        mbias[k] = mrow[(size_t)k << shift] ? 0.f : -FLT_MAX;
    }
    // ---- stage Q tile: 32x64 floats = 512 float4, 1 per thread ----
    {
        const float4* Qg = (const float4*)(Q + ((size_t)bh * TQn + q0) * DKn);
        int r = t >> 4, c4 = t & 15;
        *(float4*)&qsh[r * KST + 4 * c4] = Qg[t];
    }

    // ================= Phase A: raw scores = QK^T =================
    // warp: q rows [16qh,16qh+16), k rows [32kw,32kw+32) of tile.
    // lane: qg=l>>3 -> q rows 16qh+qg+4i (i<4); kg=l&7 -> k rows kg+8j (j<4).
    const int qg = l >> 3;
    const int kg = l & 7;
    const int qbase = 16 * qh + qg;

    for (int kt = 0; kt < 4; kt++) {
        wait_all();
        __syncthreads();                      // tile kt resident, prior writes done

        float2 acc[4][4];
        #pragma unroll
        for (int i = 0; i < 4; i++)
            #pragma unroll
            for (int j = 0; j < 4; j++) acc[i][j] = make_float2(0.f, 0.f);

        const float* kbasep = &kvsh[(32 * kw + kg) * KST];

        #pragma unroll 4
        for (int d4 = 0; d4 < 16; d4++) {
            float4 kv[4];
            #pragma unroll
            for (int j = 0; j < 4; j++)
                kv[j] = *(const float4*)&kbasep[8 * j * KST + 4 * d4];
            #pragma unroll
            for (int i = 0; i < 4; i++) {
                float4 qv = *(const float4*)&qsh[(qbase + 4 * i) * KST + 4 * d4];
                #pragma unroll
                for (int j = 0; j < 4; j++) {
                    acc[i][j] = ffma2(make_float2(qv.x, qv.y), make_float2(kv[j].x, kv[j].y), acc[i][j]);
                    acc[i][j] = ffma2(make_float2(qv.z, qv.w), make_float2(kv[j].z, kv[j].w), acc[i][j]);
                }
            }
        }

        __syncthreads();                      // all warps done reading kvsh
        // overlap: start next K tile (or V tile 0) while storing scores
        stage_tile(kv_u32, (kt < 3) ? (Kg + (size_t)(kt + 1) * KTILE * 16) : Vg, t);

        const int kb = kt * 256 + 32 * kw;
        #pragma unroll
        for (int i = 0; i < 4; i++)
            #pragma unroll
            for (int j = 0; j < 4; j++)
                scsh[(qbase + 4 * i) * SCST + kb + kg + 8 * j] = acc[i][j].x + acc[i][j].y;
    }
    __syncthreads();                          // scores complete (V0 still loading)

    // ================= softmax: warp w handles rows 2w, 2w+1 =================
    // scale (1/8) + mask bias applied here; scsh ends up holding UNNORMALIZED exp
    #pragma unroll
    for (int rr = 0; rr < 2; rr++) {
        int r = 2 * w + rr;
        float* row = &scsh[r * SCST];

        float mx = -FLT_MAX;
        #pragma unroll
        for (int i = 0; i < 8; i++) {
            float4 x = *(const float4*)&row[4 * l + 128 * i];
            float4 b = *(const float4*)&mbias[4 * l + 128 * i];
            x.x = fmaf(x.x, 0.125f, b.x);
            x.y = fmaf(x.y, 0.125f, b.y);
            x.z = fmaf(x.z, 0.125f, b.z);
            x.w = fmaf(x.w, 0.125f, b.w);
            *(float4*)&row[4 * l + 128 * i] = x;
            mx = fmaxf(mx, fmaxf(fmaxf(x.x, x.y), fmaxf(x.z, x.w)));
        }
        #pragma unroll
        for (int off = 16; off > 0; off >>= 1)
            mx = fmaxf(mx, __shfl_xor_sync(0xffffffffu, mx, off));

        float s = 0.f;
        #pragma unroll
        for (int i = 0; i < 8; i++) {
            float4 x = *(const float4*)&row[4 * l + 128 * i];
            x.x = __expf(x.x - mx);
            x.y = __expf(x.y - mx);
            x.z = __expf(x.z - mx);
            x.w = __expf(x.w - mx);
            *(float4*)&row[4 * l + 128 * i] = x;
            s += (x.x + x.y) + (x.z + x.w);
        }
        #pragma unroll
        for (int off = 16; off > 0; off >>= 1)
            s += __shfl_xor_sync(0xffffffffu, s, off);

        if (l == 0) invsh[r] = (mx == -FLT_MAX) ? 0.f : __frcp_rn(s);
    }
    __syncthreads();

    // ---- coalesced weights store (normalized on the fly) ----
    if (write_w) {
        float4* w4 = (float4*)wrow_base;
        #pragma unroll
        for (int i = 0; i < 16; i++) {
            int j  = t + i * NTHR;            // 0..8191 float4 index
            int r  = j >> 8;
            int c4 = j & 255;
            float inv = invsh[r];
            float4 e = *(const float4*)&scsh[r * SCST + 4 * c4];
            e.x *= inv; e.y *= inv; e.z *= inv; e.w *= inv;
            w4[r * 256 + c4] = e;
        }
    }

    // ================= Phase B: out = E @ V (scaled by inv at the end) =======
    // warp: q rows [16qh,+16), k rows [32kw,+32) per tile (k split 8 ways).
    // lane: qg2=l>>3 -> q rows 16qh+qg2+4i (i<4); dg=l&7 -> d floats [8dg,8dg+8).
    const int qg2 = l >> 3;
    const int dg  = l & 7;
    const int qbase2 = 16 * qh + qg2;

    float2 acc2[4][4];
    #pragma unroll
    for (int i = 0; i < 4; i++)
        #pragma unroll
        for (int c = 0; c < 4; c++) acc2[i][c] = make_float2(0.f, 0.f);

    for (int kt = 0; kt < 4; kt++) {
        wait_all();
        __syncthreads();                      // V tile kt resident

        const int kb = kt * 256 + 32 * kw;
        #pragma unroll 2
        for (int g4 = 0; g4 < 8; g4++) {
            float4 v[4][2];
            #pragma unroll
            for (int kk = 0; kk < 4; kk++) {
                const float* vr = &kvsh[(32 * kw + 4 * g4 + kk) * KST + 8 * dg];
                v[kk][0] = *(const float4*)&vr[0];
                v[kk][1] = *(const float4*)&vr[4];
            }
            #pragma unroll
            for (int i = 0; i < 4; i++) {
                float4 wf = *(const float4*)&scsh[(qbase2 + 4 * i) * SCST + kb + 4 * g4];
                acc2[i][0] = ffma2(make_float2(wf.x, wf.x), make_float2(v[0][0].x, v[0][0].y), acc2[i][0]);
                acc2[i][1] = ffma2(make_float2(wf.x, wf.x), make_float2(v[0][0].z, v[0][0].w), acc2[i][1]);
                acc2[i][2] = ffma2(make_float2(wf.x, wf.x), make_float2(v[0][1].x, v[0][1].y), acc2[i][2]);
                acc2[i][3] = ffma2(make_float2(wf.x, wf.x), make_float2(v[0][1].z, v[0][1].w), acc2[i][3]);

                acc2[i][0] = ffma2(make_float2(wf.y, wf.y), make_float2(v[1][0].x, v[1][0].y), acc2[i][0]);
                acc2[i][1] = ffma2(make_float2(wf.y, wf.y), make_float2(v[1][0].z, v[1][0].w), acc2[i][1]);
                acc2[i][2] = ffma2(make_float2(wf.y, wf.y), make_float2(v[1][1].x, v[1][1].y), acc2[i][2]);
                acc2[i][3] = ffma2(make_float2(wf.y, wf.y), make_float2(v[1][1].z, v[1][1].w), acc2[i][3]);

                acc2[i][0] = ffma2(make_float2(wf.z, wf.z), make_float2(v[2][0].x, v[2][0].y), acc2[i][0]);
                acc2[i][1] = ffma2(make_float2(wf.z, wf.z), make_float2(v[2][0].z, v[2][0].w), acc2[i][1]);
                acc2[i][2] = ffma2(make_float2(wf.z, wf.z), make_float2(v[2][1].x, v[2][1].y), acc2[i][2]);
                acc2[i][3] = ffma2(make_float2(wf.z, wf.z), make_float2(v[2][1].z, v[2][1].w), acc2[i][3]);

                acc2[i][0] = ffma2(make_float2(wf.w, wf.w), make_float2(v[3][0].x, v[3][0].y), acc2[i][0]);
                acc2[i][1] = ffma2(make_float2(wf.w, wf.w), make_float2(v[3][0].z, v[3][0].w), acc2[i][1]);
                acc2[i][2] = ffma2(make_float2(wf.w, wf.w), make_float2(v[3][1].x, v[3][1].y), acc2[i][2]);
                acc2[i][3] = ffma2(make_float2(wf.w, wf.w), make_float2(v[3][1].z, v[3][1].w), acc2[i][3]);
            }
        }

        __syncthreads();                      // all warps done reading kvsh
        if (kt < 3) stage_tile(kv_u32, Vg + (size_t)(kt + 1) * KTILE * 16, t);
    }

    // ---- cross-warp k reduction via kvsh (16 partials of [16][68]) ----
    {
        float* part = &kvsh[w * (16 * KST)];
        #pragma unroll
        for (int i = 0; i < 4; i++) {
            float* p = &part[(qg2 + 4 * i) * KST + 8 * dg];
            *(float2*)&p[0] = acc2[i][0];
            *(float2*)&p[2] = acc2[i][1];
            *(float2*)&p[4] = acc2[i][2];
            *(float2*)&p[6] = acc2[i][3];
        }
    }
    __syncthreads();
    // warp w' partial for global q row (16qh + qr) lives at kvsh[(128qh + 16kw' + qr)*KST + d]
    #pragma unroll
    for (int it = 0; it < 4; it++) {
        int idx = t + it * NTHR;              // 0..2047
        int q = idx >> 6, d = idx & 63;
        int qhh = q >> 4, qr = q & 15;
        float s = 0.f;
        #pragma unroll
        for (int kk = 0; kk < 8; kk++)
            s += kvsh[(128 * qhh + 16 * kk + qr) * KST + d];
        orow_base[(size_t)q * DKn + d] = s * invsh[q];
    }
}

// ---------------------------------------------------------------------------
extern "C" void kernel_launch(void* const* d_in, const int* in_sizes, int n_in,
                              void* d_out, int out_size) {
    const float*         Q  = (const float*)d_in[0];
    const float*         K  = (const float*)d_in[1];
    const float*         V  = (const float*)d_in[2];
    const unsigned char* Mb = (const unsigned char*)d_in[3];
    const int*           HA = (const int*)d_in[4];
    const int*           NH = (const int*)d_in[5];
    float*               O  = (float*)d_out;

    int write_w = (out_size >= (int)((size_t)BHn * TQn * (DKn + TKn))) ? 1 : 0;

    cudaFuncSetAttribute(attn_fp32x2_kernel,
                         cudaFuncAttributeMaxDynamicSharedMemorySize, SMEM_BYTES);

    detect_mask_kernel<<<1, 256>>>((const unsigned int*)Mb);

    dim3 grid(TQn / QT, BHn);
    attn_fp32x2_kernel<<<grid, NTHR, SMEM_BYTES>>>(Q, K, V, Mb, HA, NH, O, write_w);
}

// round 10
// speedup vs baseline: 1.1259x; 1.1259x over previous
#include <cuda_runtime.h>
#include <cstdint>
#include <cfloat>

#define BHn   64
#define TQn   1024
#define TKn   1024
#define DKn   64
#define QT    32
#define NTHR  256     // 8 warps, both kernels
#define KST   68      // K/V tile row stride (68%32=4 -> conflict-free)
#define SCST  1028    // score row stride
#define WST   132     // K2 weight tile row stride (132%32=4)

// ---- K1 smem: qsh[32][68] | kvsh[2][128][68] | scsh[32][1028] | mbias[1024] | invsh[32]
#define QSH_F   (QT*KST)                  // 2176
#define KVSH_F  (256*KST)                 // 17408 (two 128-row buffers)
#define SCSH_F  (QT*SCST)                 // 32896
#define SMEM1_F (QSH_F + KVSH_F + SCSH_F + TKn + 32)
#define SMEM1_B (SMEM1_F * 4)             // ~214 KB -> 1 block/SM

// ---- K2 smem: wsh[2][32][132] | vsh[2][128][68]
#define WSH_F   (32*WST)                  // 4224 per buffer
#define VSH_F   (128*KST)                 // 8704 per buffer
#define SMEM2_F (2*WSH_F + 2*VSH_F)       // 25856
#define SMEM2_B (SMEM2_F * 4)             // 103424 B -> 2 blocks/SM

// ---------------------------------------------------------------------------
__device__ int g_mask_narrow;

__global__ void detect_mask_kernel(const unsigned int* __restrict__ mw) {
    __shared__ int found;
    if (threadIdx.x == 0) found = 0;
    __syncthreads();
    int local = 0;
    for (int i = threadIdx.x; i < (BHn * TKn) / 4; i += blockDim.x) {
        if (mw[i] & 0xFFFFFF00u) local = 1;
    }
    if (local) atomicOr(&found, 1);
    __syncthreads();
    if (threadIdx.x == 0) g_mask_narrow = found;
}

// packed dual-fp32 FMA (ptxas never emits FFMA2 from C++)
__device__ __forceinline__ float2 ffma2(float2 a, float2 b, float2 c) {
    float2 d;
    asm("fma.rn.f32x2 %0, %1, %2, %3;"
        : "=l"(reinterpret_cast<unsigned long long&>(d))
        : "l"(reinterpret_cast<unsigned long long&>(a)),
          "l"(reinterpret_cast<unsigned long long&>(b)),
          "l"(reinterpret_cast<unsigned long long&>(c)));
    return d;
}

__device__ __forceinline__ unsigned int smem_u32(const void* p) {
    return (unsigned int)__cvta_generic_to_shared(p);
}
__device__ __forceinline__ void cp16(unsigned int dst, const void* src) {
    asm volatile("cp.async.cg.shared.global [%0], [%1], 16;" :: "r"(dst), "l"(src));
}
__device__ __forceinline__ void cp_commit() {
    asm volatile("cp.async.commit_group;");
}
__device__ __forceinline__ void cp_wait1() {
    asm volatile("cp.async.wait_group 1;" ::: "memory");
}
__device__ __forceinline__ void cp_wait0() {
    asm volatile("cp.async.wait_group 0;" ::: "memory");
}

// stage a 128x64 float tile (2048 float4) into smem at stride KST; 8 f4/thread
__device__ __forceinline__ void stage128(unsigned int dst_u32, const float4* __restrict__ g, int t) {
    #pragma unroll
    for (int i = 0; i < 8; i++) {
        int idx = t + i * NTHR;
        int r = idx >> 4, c4 = idx & 15;
        cp16(dst_u32 + (unsigned int)(r * KST + 4 * c4) * 4u, g + idx);
    }
    cp_commit();
}

// ===========================================================================
// K1: scores = QK^T/8 + mask -> softmax -> normalized weights to global
// one block = 32 queries x one bh head, 8 warps, double-buffered K tiles
// ===========================================================================
extern "C" __global__ void __launch_bounds__(NTHR, 1)
attn_scores_kernel(const float* __restrict__ Q, const float* __restrict__ K,
                   const unsigned char* __restrict__ Mb,
                   const int* __restrict__ pHA, const int* __restrict__ pNH,
                   float* __restrict__ Wout)
{
    extern __shared__ float sm[];
    float* qsh   = sm;                       // [32][KST]
    float* kvsh  = sm + QSH_F;               // [2][128][KST]
    float* scsh  = kvsh + KVSH_F;            // [32][SCST]
    float* mbias = scsh + SCSH_F;            // [1024]
    float* invsh = mbias + TKn;              // [32]

    const int t  = threadIdx.x;
    const int w  = t >> 5;                   // warp 0..7
    const int l  = t & 31;
    const int bh = blockIdx.y;
    const int q0 = blockIdx.x * QT;

    float* wrow_base = Wout + ((size_t)bh * TQn + q0) * TKn;

    // ---- head ablation: weights exactly zero, done ----
    if (pNH[0] > 0 && (bh % pNH[0]) == pHA[0]) {
        float4 z = make_float4(0.f, 0.f, 0.f, 0.f);
        float4* w4 = (float4*)wrow_base;
        #pragma unroll 4
        for (int i = t; i < QT * TKn / 4; i += NTHR) w4[i] = z;
        return;
    }

    const int shift = g_mask_narrow ? 0 : 2;
    const unsigned char* mrow = Mb + (((size_t)bh * TKn) << shift);
    const float4* Kg = (const float4*)(K + ((size_t)bh * TKn) * DKn);
    const unsigned int kv0 = smem_u32(kvsh);
    const unsigned int kv1 = smem_u32(kvsh + 128 * KST);

    // prestage K tiles 0 and 1
    stage128(kv0, Kg, t);
    stage128(kv1, Kg + 128 * 16, t);

    // mask bias + Q tile
    #pragma unroll
    for (int i = 0; i < 4; i++) {
        int k = t + i * NTHR;
        mbias[k] = mrow[(size_t)k << shift] ? 0.f : -FLT_MAX;
    }
    {
        const float4* Qg = (const float4*)(Q + ((size_t)bh * TQn + q0) * DKn);
        #pragma unroll
        for (int i = 0; i < 2; i++) {
            int idx = t + i * NTHR;
            int r = idx >> 4, c4 = idx & 15;
            *(float4*)&qsh[r * KST + 4 * c4] = Qg[idx];
        }
    }

    // Phase A: warp owns k rows [16w,16w+16) of each 128-row tile.
    // lane: qg=l>>2 (0..7) -> q rows qg+8i (i<4); kg=l&3 -> k rows kg+4j (j<4)
    const int qg = l >> 2;
    const int kg = l & 3;

    for (int kt = 0; kt < 8; kt++) {
        if (kt < 7) cp_wait1(); else cp_wait0();
        __syncthreads();                      // tile kt resident, prior buf reuse safe

        const float* kb_sh = &kvsh[(kt & 1) * 128 * KST + (16 * w + kg) * KST];

        float2 acc[4][4];
        #pragma unroll
        for (int i = 0; i < 4; i++)
            #pragma unroll
            for (int j = 0; j < 4; j++) acc[i][j] = make_float2(0.f, 0.f);

        #pragma unroll 4
        for (int d4 = 0; d4 < 16; d4++) {
            float4 kv[4];
            #pragma unroll
            for (int j = 0; j < 4; j++)
                kv[j] = *(const float4*)&kb_sh[4 * j * KST + 4 * d4];
            #pragma unroll
            for (int i = 0; i < 4; i++) {
                float4 qv = *(const float4*)&qsh[(qg + 8 * i) * KST + 4 * d4];
                #pragma unroll
                for (int j = 0; j < 4; j++) {
                    acc[i][j] = ffma2(make_float2(qv.x, qv.y), make_float2(kv[j].x, kv[j].y), acc[i][j]);
                    acc[i][j] = ffma2(make_float2(qv.z, qv.w), make_float2(kv[j].z, kv[j].w), acc[i][j]);
                }
            }
        }

        __syncthreads();                      // all warps done with this buffer
        if (kt < 6) stage128((kt & 1) ? kv1 : kv0, Kg + (size_t)(kt + 2) * 128 * 16, t);

        const int kb = kt * 128 + 16 * w;
        #pragma unroll
        for (int i = 0; i < 4; i++)
            #pragma unroll
            for (int j = 0; j < 4; j++)
                scsh[(qg + 8 * i) * SCST + kb + kg + 4 * j] = acc[i][j].x + acc[i][j].y;
    }
    __syncthreads();

    // softmax: warp w handles rows 4w..4w+3; scale + mask bias fused
    #pragma unroll
    for (int rr = 0; rr < 4; rr++) {
        int r = 4 * w + rr;
        float* row = &scsh[r * SCST];

        float mx = -FLT_MAX;
        #pragma unroll
        for (int i = 0; i < 8; i++) {
            float4 x = *(const float4*)&row[4 * l + 128 * i];
            float4 b = *(const float4*)&mbias[4 * l + 128 * i];
            x.x = fmaf(x.x, 0.125f, b.x);
            x.y = fmaf(x.y, 0.125f, b.y);
            x.z = fmaf(x.z, 0.125f, b.z);
            x.w = fmaf(x.w, 0.125f, b.w);
            *(float4*)&row[4 * l + 128 * i] = x;
            mx = fmaxf(mx, fmaxf(fmaxf(x.x, x.y), fmaxf(x.z, x.w)));
        }
        #pragma unroll
        for (int off = 16; off > 0; off >>= 1)
            mx = fmaxf(mx, __shfl_xor_sync(0xffffffffu, mx, off));

        float s = 0.f;
        #pragma unroll
        for (int i = 0; i < 8; i++) {
            float4 x = *(const float4*)&row[4 * l + 128 * i];
            x.x = __expf(x.x - mx);
            x.y = __expf(x.y - mx);
            x.z = __expf(x.z - mx);
            x.w = __expf(x.w - mx);
            *(float4*)&row[4 * l + 128 * i] = x;
            s += (x.x + x.y) + (x.z + x.w);
        }
        #pragma unroll
        for (int off = 16; off > 0; off >>= 1)
            s += __shfl_xor_sync(0xffffffffu, s, off);

        if (l == 0) invsh[r] = (mx == -FLT_MAX) ? 0.f : __frcp_rn(s);
    }
    __syncthreads();

    // normalized weights -> global (coalesced float4)
    {
        float4* w4 = (float4*)wrow_base;
        #pragma unroll
        for (int i = 0; i < 32; i++) {
            int j  = t + i * NTHR;            // 0..8191
            int r  = j >> 8;
            int c4 = j & 255;
            float inv = invsh[r];
            float4 e = *(const float4*)&scsh[r * SCST + 4 * c4];
            e.x *= inv; e.y *= inv; e.z *= inv; e.w *= inv;
            w4[r * 256 + c4] = e;
        }
    }
}

// ===========================================================================
// K2: O = W @ V   (W already normalized; ablated/fully-masked rows are 0)
// one block = 32 queries x one bh head, 8 warps, 2 blocks/SM, double-buffered
// ===========================================================================
extern "C" __global__ void __launch_bounds__(NTHR, 2)
attn_out_kernel(const float* __restrict__ V, const float* __restrict__ W,
                float* __restrict__ O)
{
    extern __shared__ float sm[];
    float* wsh = sm;                          // [2][32][WST]
    float* vsh = sm + 2 * WSH_F;              // [2][128][KST] (reused for reduction)

    const int t  = threadIdx.x;
    const int w  = t >> 5;
    const int l  = t & 31;
    const int bh = blockIdx.y;
    const int q0 = blockIdx.x * QT;

    const float4* Vg = (const float4*)(V + ((size_t)bh * TKn) * DKn);
    const float4* Wg = (const float4*)(W + ((size_t)bh * TQn + q0) * TKn);
    float* orow_base = O + ((size_t)bh * TQn + q0) * DKn;

    const unsigned int wsh_u = smem_u32(wsh);
    const unsigned int vsh_u = smem_u32(vsh);

    // stage one tile (W 32x128 + V 128x64) into buffer b
    auto stage = [&](int b, int kt) {
        unsigned int wd = wsh_u + (unsigned int)(b * WSH_F) * 4u;
        #pragma unroll
        for (int i = 0; i < 4; i++) {
            int idx = t + i * NTHR;           // 0..1023 : W f4
            int r = idx >> 5, c4 = idx & 31;
            cp16(wd + (unsigned int)(r * WST + 4 * c4) * 4u, Wg + (size_t)r * 256 + kt * 32 + c4);
        }
        unsigned int vd = vsh_u + (unsigned int)(b * VSH_F) * 4u;
        #pragma unroll
        for (int i = 0; i < 8; i++) {
            int idx = t + i * NTHR;           // 0..2047 : V f4
            int r = idx >> 4, c4 = idx & 15;
            cp16(vd + (unsigned int)(r * KST + 4 * c4) * 4u, Vg + (size_t)(kt * 128 + r) * 16 + c4);
        }
        cp_commit();
    };

    stage(0, 0);
    stage(1, 1);

    // warp owns k rows [16w,16w+16) per tile; lane: qg2=l>>3 -> q rows qg2+4i (i<8);
    // dg=l&7 -> d floats [8dg,8dg+8)
    const int qg2 = l >> 3;
    const int dg  = l & 7;

    float2 acc2[8][4];
    #pragma unroll
    for (int i = 0; i < 8; i++)
        #pragma unroll
        for (int c = 0; c < 4; c++) acc2[i][c] = make_float2(0.f, 0.f);

    for (int kt = 0; kt < 8; kt++) {
        if (kt < 7) cp_wait1(); else cp_wait0();
        __syncthreads();

        const float* vb = &vsh[(kt & 1) * VSH_F];
        const float* wb = &wsh[(kt & 1) * WSH_F];

        #pragma unroll 2
        for (int g4 = 0; g4 < 4; g4++) {
            float4 v[4][2];
            #pragma unroll
            for (int kk = 0; kk < 4; kk++) {
                const float* vr = &vb[(16 * w + 4 * g4 + kk) * KST + 8 * dg];
                v[kk][0] = *(const float4*)&vr[0];
                v[kk][1] = *(const float4*)&vr[4];
            }
            #pragma unroll
            for (int i = 0; i < 8; i++) {
                float4 wf = *(const float4*)&wb[(qg2 + 4 * i) * WST + 16 * w + 4 * g4];
                acc2[i][0] = ffma2(make_float2(wf.x, wf.x), make_float2(v[0][0].x, v[0][0].y), acc2[i][0]);
                acc2[i][1] = ffma2(make_float2(wf.x, wf.x), make_float2(v[0][0].z, v[0][0].w), acc2[i][1]);
                acc2[i][2] = ffma2(make_float2(wf.x, wf.x), make_float2(v[0][1].x, v[0][1].y), acc2[i][2]);
                acc2[i][3] = ffma2(make_float2(wf.x, wf.x), make_float2(v[0][1].z, v[0][1].w), acc2[i][3]);

                acc2[i][0] = ffma2(make_float2(wf.y, wf.y), make_float2(v[1][0].x, v[1][0].y), acc2[i][0]);
                acc2[i][1] = ffma2(make_float2(wf.y, wf.y), make_float2(v[1][0].z, v[1][0].w), acc2[i][1]);
                acc2[i][2] = ffma2(make_float2(wf.y, wf.y), make_float2(v[1][1].x, v[1][1].y), acc2[i][2]);
                acc2[i][3] = ffma2(make_float2(wf.y, wf.y), make_float2(v[1][1].z, v[1][1].w), acc2[i][3]);

                acc2[i][0] = ffma2(make_float2(wf.z, wf.z), make_float2(v[2][0].x, v[2][0].y), acc2[i][0]);
                acc2[i][1] = ffma2(make_float2(wf.z, wf.z), make_float2(v[2][0].z, v[2][0].w), acc2[i][1]);
                acc2[i][2] = ffma2(make_float2(wf.z, wf.z), make_float2(v[2][1].x, v[2][1].y), acc2[i][2]);
                acc2[i][3] = ffma2(make_float2(wf.z, wf.z), make_float2(v[2][1].z, v[2][1].w), acc2[i][3]);

                acc2[i][0] = ffma2(make_float2(wf.w, wf.w), make_float2(v[3][0].x, v[3][0].y), acc2[i][0]);
                acc2[i][1] = ffma2(make_float2(wf.w, wf.w), make_float2(v[3][0].z, v[3][0].w), acc2[i][1]);
                acc2[i][2] = ffma2(make_float2(wf.w, wf.w), make_float2(v[3][1].x, v[3][1].y), acc2[i][2]);
                acc2[i][3] = ffma2(make_float2(wf.w, wf.w), make_float2(v[3][1].z, v[3][1].w), acc2[i][3]);
            }
        }

        __syncthreads();
        if (kt < 6) stage(kt & 1, kt + 2);
    }

    // cross-warp k reduction via vsh (8 partials of [32][KST])
    {
        float* part = &vsh[w * (32 * KST)];
        #pragma unroll
        for (int i = 0; i < 8; i++) {
            float* p = &part[(qg2 + 4 * i) * KST + 8 * dg];
            *(float2*)&p[0] = acc2[i][0];
            *(float2*)&p[2] = acc2[i][1];
            *(float2*)&p[4] = acc2[i][2];
            *(float2*)&p[6] = acc2[i][3];
        }
    }
    __syncthreads();
    #pragma unroll
    for (int it = 0; it < 8; it++) {
        int idx = t + it * NTHR;              // 0..2047
        int q = idx >> 6, d = idx & 63;
        float s = 0.f;
        #pragma unroll
        for (int kk = 0; kk < 8; kk++)
            s += vsh[kk * (32 * KST) + q * KST + d];
        orow_base[(size_t)q * DKn + d] = s;
    }
}

// ---------------------------------------------------------------------------
extern "C" void kernel_launch(void* const* d_in, const int* in_sizes, int n_in,
                              void* d_out, int out_size) {
    const float*         Q  = (const float*)d_in[0];
    const float*         K  = (const float*)d_in[1];
    const float*         V  = (const float*)d_in[2];
    const unsigned char* Mb = (const unsigned char*)d_in[3];
    const int*           HA = (const int*)d_in[4];
    const int*           NH = (const int*)d_in[5];
    float*               O  = (float*)d_out;
    float*               W  = O + (size_t)BHn * TQn * DKn;

    cudaFuncSetAttribute(attn_scores_kernel,
                         cudaFuncAttributeMaxDynamicSharedMemorySize, SMEM1_B);
    cudaFuncSetAttribute(attn_out_kernel,
                         cudaFuncAttributeMaxDynamicSharedMemorySize, SMEM2_B);

    detect_mask_kernel<<<1, 256>>>((const unsigned int*)Mb);

    dim3 grid(TQn / QT, BHn);
    attn_scores_kernel<<<grid, NTHR, SMEM1_B>>>(Q, K, Mb, HA, NH, W);
    attn_out_kernel<<<grid, NTHR, SMEM2_B>>>(V, W, O);
}

// round 11
// speedup vs baseline: 1.1266x; 1.0007x over previous
#include <cuda_runtime.h>
#include <cstdint>
#include <cfloat>

#define BHn   64
#define TQn   1024
#define TKn   1024
#define DKn   64
#define QT    32
#define NTHR  256     // 8 warps, both kernels
#define KST   68      // K/V tile row stride (68%32=4 -> conflict-free)
#define SCST  1028    // score row stride
#define WST   132     // K2 weight tile row stride (132%32=4)

// ---- K1 smem: qsh[32][68] | kvsh[2][128][68] | scsh[32][1028] | mbias[1024] | invsh[32]
#define QSH_F   (QT*KST)                  // 2176
#define KVSH_F  (256*KST)                 // 17408 (two 128-row buffers)
#define SCSH_F  (QT*SCST)                 // 32896
#define SMEM1_F (QSH_F + KVSH_F + SCSH_F + TKn + 32)
#define SMEM1_B (SMEM1_F * 4)             // ~214 KB -> 1 block/SM

// ---- K2 smem: wsh[2][32][132] | vsh[2][128][68]
#define WSH_F   (32*WST)                  // 4224 per buffer
#define VSH_F   (128*KST)                 // 8704 per buffer
#define SMEM2_F (2*WSH_F + 2*VSH_F)       // 25856
#define SMEM2_B (SMEM2_F * 4)             // 103424 B -> 2 blocks/SM

// ---------------------------------------------------------------------------
__device__ int g_mask_narrow;

__global__ void detect_mask_kernel(const unsigned int* __restrict__ mw) {
    __shared__ int found;
    if (threadIdx.x == 0) found = 0;
    __syncthreads();
    int local = 0;
    for (int i = threadIdx.x; i < (BHn * TKn) / 4; i += blockDim.x) {
        if (mw[i] & 0xFFFFFF00u) local = 1;
    }
    if (local) atomicOr(&found, 1);
    __syncthreads();
    if (threadIdx.x == 0) g_mask_narrow = found;
}

// packed dual-fp32 FMA (ptxas never emits FFMA2 from C++)
__device__ __forceinline__ float2 ffma2(float2 a, float2 b, float2 c) {
    float2 d;
    asm("fma.rn.f32x2 %0, %1, %2, %3;"
        : "=l"(reinterpret_cast<unsigned long long&>(d))
        : "l"(reinterpret_cast<unsigned long long&>(a)),
          "l"(reinterpret_cast<unsigned long long&>(b)),
          "l"(reinterpret_cast<unsigned long long&>(c)));
    return d;
}

__device__ __forceinline__ unsigned int smem_u32(const void* p) {
    return (unsigned int)__cvta_generic_to_shared(p);
}
__device__ __forceinline__ void cp16(unsigned int dst, const void* src) {
    asm volatile("cp.async.cg.shared.global [%0], [%1], 16;" :: "r"(dst), "l"(src));
}
__device__ __forceinline__ void cp_commit() {
    asm volatile("cp.async.commit_group;");
}
__device__ __forceinline__ void cp_wait1() {
    asm volatile("cp.async.wait_group 1;" ::: "memory");
}
__device__ __forceinline__ void cp_wait0() {
    asm volatile("cp.async.wait_group 0;" ::: "memory");
}

// stage a 128x64 float tile (2048 float4) into smem at stride KST; 8 f4/thread
__device__ __forceinline__ void stage128(unsigned int dst_u32, const float4* __restrict__ g, int t) {
    #pragma unroll
    for (int i = 0; i < 8; i++) {
        int idx = t + i * NTHR;
        int r = idx >> 4, c4 = idx & 15;
        cp16(dst_u32 + (unsigned int)(r * KST + 4 * c4) * 4u, g + idx);
    }
    cp_commit();
}

// ===========================================================================
// K1: scores = QK^T/8 + mask -> softmax -> normalized weights to global
// one block = 32 queries x one bh head, 8 warps, double-buffered K tiles
// ===========================================================================
extern "C" __global__ void __launch_bounds__(NTHR, 1)
attn_scores_kernel(const float* __restrict__ Q, const float* __restrict__ K,
                   const unsigned char* __restrict__ Mb,
                   const int* __restrict__ pHA, const int* __restrict__ pNH,
                   float* __restrict__ Wout)
{
    extern __shared__ float sm[];
    float* qsh   = sm;                       // [32][KST]
    float* kvsh  = sm + QSH_F;               // [2][128][KST]
    float* scsh  = kvsh + KVSH_F;            // [32][SCST]
    float* mbias = scsh + SCSH_F;            // [1024]
    float* invsh = mbias + TKn;              // [32]

    const int t  = threadIdx.x;
    const int w  = t >> 5;                   // warp 0..7
    const int l  = t & 31;
    const int bh = blockIdx.y;
    const int q0 = blockIdx.x * QT;

    float* wrow_base = Wout + ((size_t)bh * TQn + q0) * TKn;

    // ---- head ablation: weights exactly zero, done ----
    if (pNH[0] > 0 && (bh % pNH[0]) == pHA[0]) {
        float4 z = make_float4(0.f, 0.f, 0.f, 0.f);
        float4* w4 = (float4*)wrow_base;
        #pragma unroll 4
        for (int i = t; i < QT * TKn / 4; i += NTHR) w4[i] = z;
        return;
    }

    const int shift = g_mask_narrow ? 0 : 2;
    const unsigned char* mrow = Mb + (((size_t)bh * TKn) << shift);
    const float4* Kg = (const float4*)(K + ((size_t)bh * TKn) * DKn);
    const unsigned int kv0 = smem_u32(kvsh);
    const unsigned int kv1 = smem_u32(kvsh + 128 * KST);

    // prestage K tiles 0 and 1
    stage128(kv0, Kg, t);
    stage128(kv1, Kg + 128 * 16, t);

    // mask bias + Q tile
    #pragma unroll
    for (int i = 0; i < 4; i++) {
        int k = t + i * NTHR;
        mbias[k] = mrow[(size_t)k << shift] ? 0.f : -FLT_MAX;
    }
    {
        const float4* Qg = (const float4*)(Q + ((size_t)bh * TQn + q0) * DKn);
        #pragma unroll
        for (int i = 0; i < 2; i++) {
            int idx = t + i * NTHR;
            int r = idx >> 4, c4 = idx & 15;
            *(float4*)&qsh[r * KST + 4 * c4] = Qg[idx];
        }
    }

    // Phase A: warp owns k rows [16w,16w+16) of each 128-row tile.
    // lane: qg=l>>2 (0..7) -> q rows qg+8i (i<4); kg=l&3 -> k rows kg+4j (j<4)
    const int qg = l >> 2;
    const int kg = l & 3;

    for (int kt = 0; kt < 8; kt++) {
        if (kt < 7) cp_wait1(); else cp_wait0();
        __syncthreads();                      // tile kt resident, prior buf reuse safe

        const float* kb_sh = &kvsh[(kt & 1) * 128 * KST + (16 * w + kg) * KST];

        float2 acc[4][4];
        #pragma unroll
        for (int i = 0; i < 4; i++)
            #pragma unroll
            for (int j = 0; j < 4; j++) acc[i][j] = make_float2(0.f, 0.f);

        #pragma unroll 4
        for (int d4 = 0; d4 < 16; d4++) {
            float4 kv[4];
            #pragma unroll
            for (int j = 0; j < 4; j++)
                kv[j] = *(const float4*)&kb_sh[4 * j * KST + 4 * d4];
            #pragma unroll
            for (int i = 0; i < 4; i++) {
                float4 qv = *(const float4*)&qsh[(qg + 8 * i) * KST + 4 * d4];
                #pragma unroll
                for (int j = 0; j < 4; j++) {
                    acc[i][j] = ffma2(make_float2(qv.x, qv.y), make_float2(kv[j].x, kv[j].y), acc[i][j]);
                    acc[i][j] = ffma2(make_float2(qv.z, qv.w), make_float2(kv[j].z, kv[j].w), acc[i][j]);
                }
            }
        }

        __syncthreads();                      // all warps done with this buffer
        if (kt < 6) stage128((kt & 1) ? kv1 : kv0, Kg + (size_t)(kt + 2) * 128 * 16, t);

        const int kb = kt * 128 + 16 * w;
        #pragma unroll
        for (int i = 0; i < 4; i++)
            #pragma unroll
            for (int j = 0; j < 4; j++)
                scsh[(qg + 8 * i) * SCST + kb + kg + 4 * j] = acc[i][j].x + acc[i][j].y;
    }
    __syncthreads();

    // softmax: warp w handles rows 4w..4w+3; scale + mask bias fused
    #pragma unroll
    for (int rr = 0; rr < 4; rr++) {
        int r = 4 * w + rr;
        float* row = &scsh[r * SCST];

        float mx = -FLT_MAX;
        #pragma unroll
        for (int i = 0; i < 8; i++) {
            float4 x = *(const float4*)&row[4 * l + 128 * i];
            float4 b = *(const float4*)&mbias[4 * l + 128 * i];
            x.x = fmaf(x.x, 0.125f, b.x);
            x.y = fmaf(x.y, 0.125f, b.y);
            x.z = fmaf(x.z, 0.125f, b.z);
            x.w = fmaf(x.w, 0.125f, b.w);
            *(float4*)&row[4 * l + 128 * i] = x;
            mx = fmaxf(mx, fmaxf(fmaxf(x.x, x.y), fmaxf(x.z, x.w)));
        }
        #pragma unroll
        for (int off = 16; off > 0; off >>= 1)
            mx = fmaxf(mx, __shfl_xor_sync(0xffffffffu, mx, off));

        float s = 0.f;
        #pragma unroll
        for (int i = 0; i < 8; i++) {
            float4 x = *(const float4*)&row[4 * l + 128 * i];
            x.x = __expf(x.x - mx);
            x.y = __expf(x.y - mx);
            x.z = __expf(x.z - mx);
            x.w = __expf(x.w - mx);
            *(float4*)&row[4 * l + 128 * i] = x;
            s += (x.x + x.y) + (x.z + x.w);
        }
        #pragma unroll
        for (int off = 16; off > 0; off >>= 1)
            s += __shfl_xor_sync(0xffffffffu, s, off);

        if (l == 0) invsh[r] = (mx == -FLT_MAX) ? 0.f : __frcp_rn(s);
    }
    __syncthreads();

    // normalized weights -> global (coalesced float4)
    {
        float4* w4 = (float4*)wrow_base;
        #pragma unroll
        for (int i = 0; i < 32; i++) {
            int j  = t + i * NTHR;            // 0..8191
            int r  = j >> 8;
            int c4 = j & 255;
            float inv = invsh[r];
            float4 e = *(const float4*)&scsh[r * SCST + 4 * c4];
            e.x *= inv; e.y *= inv; e.z *= inv; e.w *= inv;
            w4[r * 256 + c4] = e;
        }
    }
}

// ===========================================================================
// K2: O = W @ V   (W already normalized; ablated/fully-masked rows are 0)
// one block = 32 queries x one bh head, 8 warps, 2 blocks/SM, double-buffered
// ===========================================================================
extern "C" __global__ void __launch_bounds__(NTHR, 2)
attn_out_kernel(const float* __restrict__ V, const float* __restrict__ W,
                float* __restrict__ O)
{
    extern __shared__ float sm[];
    float* wsh = sm;                          // [2][32][WST]
    float* vsh = sm + 2 * WSH_F;              // [2][128][KST] (reused for reduction)

    const int t  = threadIdx.x;
    const int w  = t >> 5;
    const int l  = t & 31;
    const int bh = blockIdx.y;
    const int q0 = blockIdx.x * QT;

    const float4* Vg = (const float4*)(V + ((size_t)bh * TKn) * DKn);
    const float4* Wg = (const float4*)(W + ((size_t)bh * TQn + q0) * TKn);
    float* orow_base = O + ((size_t)bh * TQn + q0) * DKn;

    const unsigned int wsh_u = smem_u32(wsh);
    const unsigned int vsh_u = smem_u32(vsh);

    // stage one tile (W 32x128 + V 128x64) into buffer b
    auto stage = [&](int b, int kt) {
        unsigned int wd = wsh_u + (unsigned int)(b * WSH_F) * 4u;
        #pragma unroll
        for (int i = 0; i < 4; i++) {
            int idx = t + i * NTHR;           // 0..1023 : W f4
            int r = idx >> 5, c4 = idx & 31;
            cp16(wd + (unsigned int)(r * WST + 4 * c4) * 4u, Wg + (size_t)r * 256 + kt * 32 + c4);
        }
        unsigned int vd = vsh_u + (unsigned int)(b * VSH_F) * 4u;
        #pragma unroll
        for (int i = 0; i < 8; i++) {
            int idx = t + i * NTHR;           // 0..2047 : V f4
            int r = idx >> 4, c4 = idx & 15;
            cp16(vd + (unsigned int)(r * KST + 4 * c4) * 4u, Vg + (size_t)(kt * 128 + r) * 16 + c4);
        }
        cp_commit();
    };

    stage(0, 0);
    stage(1, 1);

    // warp owns k rows [16w,16w+16) per tile; lane: qg2=l>>3 -> q rows qg2+4i (i<8);
    // dg=l&7 -> d floats [8dg,8dg+8)
    const int qg2 = l >> 3;
    const int dg  = l & 7;

    float2 acc2[8][4];
    #pragma unroll
    for (int i = 0; i < 8; i++)
        #pragma unroll
        for (int c = 0; c < 4; c++) acc2[i][c] = make_float2(0.f, 0.f);

    for (int kt = 0; kt < 8; kt++) {
        if (kt < 7) cp_wait1(); else cp_wait0();
        __syncthreads();

        const float* vb = &vsh[(kt & 1) * VSH_F];
        const float* wb = &wsh[(kt & 1) * WSH_F];

        #pragma unroll 2
        for (int g4 = 0; g4 < 4; g4++) {
            float4 v[4][2];
            #pragma unroll
            for (int kk = 0; kk < 4; kk++) {
                const float* vr = &vb[(16 * w + 4 * g4 + kk) * KST + 8 * dg];
                v[kk][0] = *(const float4*)&vr[0];
                v[kk][1] = *(const float4*)&vr[4];
            }
            #pragma unroll
            for (int i = 0; i < 8; i++) {
                float4 wf = *(const float4*)&wb[(qg2 + 4 * i) * WST + 16 * w + 4 * g4];
                acc2[i][0] = ffma2(make_float2(wf.x, wf.x), make_float2(v[0][0].x, v[0][0].y), acc2[i][0]);
                acc2[i][1] = ffma2(make_float2(wf.x, wf.x), make_float2(v[0][0].z, v[0][0].w), acc2[i][1]);
                acc2[i][2] = ffma2(make_float2(wf.x, wf.x), make_float2(v[0][1].x, v[0][1].y), acc2[i][2]);
                acc2[i][3] = ffma2(make_float2(wf.x, wf.x), make_float2(v[0][1].z, v[0][1].w), acc2[i][3]);

                acc2[i][0] = ffma2(make_float2(wf.y, wf.y), make_float2(v[1][0].x, v[1][0].y), acc2[i][0]);
                acc2[i][1] = ffma2(make_float2(wf.y, wf.y), make_float2(v[1][0].z, v[1][0].w), acc2[i][1]);
                acc2[i][2] = ffma2(make_float2(wf.y, wf.y), make_float2(v[1][1].x, v[1][1].y), acc2[i][2]);
                acc2[i][3] = ffma2(make_float2(wf.y, wf.y), make_float2(v[1][1].z, v[1][1].w), acc2[i][3]);

                acc2[i][0] = ffma2(make_float2(wf.z, wf.z), make_float2(v[2][0].x, v[2][0].y), acc2[i][0]);
                acc2[i][1] = ffma2(make_float2(wf.z, wf.z), make_float2(v[2][0].z, v[2][0].w), acc2[i][1]);
                acc2[i][2] = ffma2(make_float2(wf.z, wf.z), make_float2(v[2][1].x, v[2][1].y), acc2[i][2]);
                acc2[i][3] = ffma2(make_float2(wf.z, wf.z), make_float2(v[2][1].z, v[2][1].w), acc2[i][3]);

                acc2[i][0] = ffma2(make_float2(wf.w, wf.w), make_float2(v[3][0].x, v[3][0].y), acc2[i][0]);
                acc2[i][1] = ffma2(make_float2(wf.w, wf.w), make_float2(v[3][0].z, v[3][0].w), acc2[i][1]);
                acc2[i][2] = ffma2(make_float2(wf.w, wf.w), make_float2(v[3][1].x, v[3][1].y), acc2[i][2]);
                acc2[i][3] = ffma2(make_float2(wf.w, wf.w), make_float2(v[3][1].z, v[3][1].w), acc2[i][3]);
            }
        }

        __syncthreads();
        if (kt < 6) stage(kt & 1, kt + 2);
    }

    // cross-warp k reduction via vsh (8 partials of [32][KST])
    {
        float* part = &vsh[w * (32 * KST)];
        #pragma unroll
        for (int i = 0; i < 8; i++) {
            float* p = &part[(qg2 + 4 * i) * KST + 8 * dg];
            *(float2*)&p[0] = acc2[i][0];
            *(float2*)&p[2] = acc2[i][1];
            *(float2*)&p[4] = acc2[i][2];
            *(float2*)&p[6] = acc2[i][3];
        }
    }
    __syncthreads();
    #pragma unroll
    for (int it = 0; it < 8; it++) {
        int idx = t + it * NTHR;              // 0..2047
        int q = idx >> 6, d = idx & 63;
        float s = 0.f;
        #pragma unroll
        for (int kk = 0; kk < 8; kk++)
            s += vsh[kk * (32 * KST) + q * KST + d];
        orow_base[(size_t)q * DKn + d] = s;
    }
}

// ---------------------------------------------------------------------------
extern "C" void kernel_launch(void* const* d_in, const int* in_sizes, int n_in,
                              void* d_out, int out_size) {
    const float*         Q  = (const float*)d_in[0];
    const float*         K  = (const float*)d_in[1];
    const float*         V  = (const float*)d_in[2];
    const unsigned char* Mb = (const unsigned char*)d_in[3];
    const int*           HA = (const int*)d_in[4];
    const int*           NH = (const int*)d_in[5];
    float*               O  = (float*)d_out;
    float*               W  = O + (size_t)BHn * TQn * DKn;

    cudaFuncSetAttribute(attn_scores_kernel,
                         cudaFuncAttributeMaxDynamicSharedMemorySize, SMEM1_B);
    cudaFuncSetAttribute(attn_out_kernel,
                         cudaFuncAttributeMaxDynamicSharedMemorySize, SMEM2_B);

    detect_mask_kernel<<<1, 256>>>((const unsigned int*)Mb);

    dim3 grid(TQn / QT, BHn);
    attn_scores_kernel<<<grid, NTHR, SMEM1_B>>>(Q, K, Mb, HA, NH, W);
    attn_out_kernel<<<grid, NTHR, SMEM2_B>>>(V, W, O);
}